// round 16
// baseline (speedup 1.0000x reference)
#include <cuda_runtime.h>

// Fixed problem shapes
#define BD 2
#define FD 32
#define CD 5
#define DHW 884736           // 96^3
#define Q4 (DHW/4)           // 221184 (= 216 * 1024)
#define NVOX (BD*DHW)        // 1769472
#define NG (NVOX/4)          // 442368
#define NFEAT (BD*FD*DHW)    // 56623104
#define PLO 15872            // conf in (0.19,1.0] -> 16-bit prefix within [PLO, PLO+512)
#define NBIN 512
#define NSLOT 20             // 5 classes x 4 order statistics
#define NENT 20
#define SPIKE_PRE 16256      // 0x3F80 : bin containing only conf == 1.0
#define HGRID 592            // exactly 4 CTAs/SM x 148 SMs -> all co-resident
#define SGRID (NG/1024)      // 432 blocks x 512 threads x 2 tiles
#define MAXSAV 3             // ceil(NG / (HGRID*256)) = 3 voxel-groups per thread

// ---------------- device scratch ----------------
__device__ __align__(16) unsigned g_packed[NVOX];        // label<<29 | (conf bits & 0x1FFFFFFF)
__device__ unsigned g_hist1[CD * NBIN];
__device__ __align__(16) unsigned g_histF[NENT * 65536]; // fine 16-bit histograms (5.24 MB)
__device__ __align__(16) unsigned g_chunk[NENT * 256];   // 256-chunk sums per entry
__device__ float    g_newmin[CD], g_newmax[CD];
__device__ unsigned g_bar;                               // grid barrier counter
__device__ unsigned g_done;                              // last-block counter

// ---------------- K0: zero hist1 + counters ----------------
__global__ void k_zero() {
    int i = blockIdx.x * blockDim.x + threadIdx.x;
    int stride = gridDim.x * blockDim.x;
    for (int j = i; j < CD * NBIN; j += stride) g_hist1[j] = 0;
    if (i == 0) { g_bar = 0; g_done = 0; }
}

// ---------------- K1: fused conf + hist1 + grid barrier + fine + finalize ---------
__device__ __forceinline__ float conf5(float a, float b, float c, float d, float e) {
    float y0 = a * 10.0f, y1 = b * 10.0f, y2 = c * 10.0f, y3 = d * 10.0f, y4 = e * 10.0f;
    float m = fmaxf(fmaxf(fmaxf(y0, y1), fmaxf(y2, y3)), y4);
    float s = __expf(y0 - m) + __expf(y1 - m) + __expf(y2 - m) + __expf(y3 - m) + __expf(y4 - m);
    return __fdividef(1.0f, s);
}

__global__ __launch_bounds__(256, 4)
void k_fused(const float4* __restrict__ lg, const int4* __restrict__ lb,
             const float* __restrict__ emin, const float* __restrict__ emax,
             const unsigned char* __restrict__ einit) {
    __shared__ unsigned sh[CD * NBIN];      // level-1 histogram (10 KB)
    __shared__ int      spre[NSLOT];
    __shared__ unsigned srank[NSLOT];
    __shared__ int      sek[NENT];
    __shared__ unsigned utgt[CD];
    __shared__ int      s_m;
    __shared__ unsigned swsum[8], swpre[8];
    __shared__ unsigned s_n;
    __shared__ unsigned s_ncls[CD];
    __shared__ double   s_f05[CD], s_f95[CD];
    __shared__ unsigned sx[NSLOT];
    __shared__ bool     is_last;

    int t = threadIdx.x, lane = t & 31, warp = t >> 5;
    for (int j = t; j < CD * NBIN; j += blockDim.x) sh[j] = 0;
    __syncthreads();

    int stride = gridDim.x * blockDim.x;
    int tid = blockIdx.x * blockDim.x + t;

    // zero fine histograms + chunk sums (consumed after the grid barrier)
    {
        uint4 z = make_uint4(0, 0, 0, 0);
        for (int j = tid; j < (NENT * 65536) / 4; j += stride) __stcs((uint4*)g_histF + j, z);
        for (int j = tid; j < (NENT * 256) / 4; j += stride)   ((uint4*)g_chunk)[j] = z;
    }

    // ---- phase A: confidence + packed store + smem level-1 histogram ----
    uint4 pk_sav[MAXSAV];
    int nsav = 0;
    for (int g = tid; g < NG; g += stride) {
        int v = g * 4;
        int b = (v >= DHW) ? 1 : 0;
        int s4 = g - b * Q4;
        size_t base = (size_t)(b * CD) * Q4 + (size_t)s4;
        float4 L0 = __ldcs(&lg[base]);
        float4 L1 = __ldcs(&lg[base + Q4]);
        float4 L2 = __ldcs(&lg[base + 2 * (size_t)Q4]);
        float4 L3 = __ldcs(&lg[base + 3 * (size_t)Q4]);
        float4 L4 = __ldcs(&lg[base + 4 * (size_t)Q4]);
        float cf[4];
        cf[0] = conf5(L0.x, L1.x, L2.x, L3.x, L4.x);
        cf[1] = conf5(L0.y, L1.y, L2.y, L3.y, L4.y);
        cf[2] = conf5(L0.z, L1.z, L2.z, L3.z, L4.z);
        cf[3] = conf5(L0.w, L1.w, L2.w, L3.w, L4.w);
        int4 li = __ldcs(&lb[g]);
        int cc[4] = { li.x, li.y, li.z, li.w };
        unsigned pk[4];
#pragma unroll
        for (int k = 0; k < 4; k++) {
            unsigned bits = __float_as_uint(cf[k]);
            pk[k] = ((unsigned)cc[k] << 29) | (bits & 0x1FFFFFFFu);
            unsigned idx = (bits >> 16) - PLO;
            if (idx < NBIN) atomicAdd(&sh[cc[k] * NBIN + idx], 1u);
        }
        uint4 q = make_uint4(pk[0], pk[1], pk[2], pk[3]);
        pk_sav[nsav++] = q;
        __stcs((uint4*)g_packed + g, q);
    }
    __syncthreads();
    for (int j = t; j < CD * NBIN; j += blockDim.x) {
        unsigned u = sh[j];
        if (u) atomicAdd(&g_hist1[j], u);
    }

    // ---- grid barrier (all 592 CTAs co-resident by construction) ----
    __threadfence();
    __syncthreads();
    if (t == 0) {
        atomicAdd(&g_bar, 1u);
        while (*(volatile unsigned*)&g_bar < (unsigned)gridDim.x) { }
        __threadfence();
    }
    __syncthreads();

    // ---- phase B: find2 on complete hist1 (recomputed per block) ----
    if (t < NSLOT) { spre[t] = -1; srank[t] = 0; }
    __syncthreads();
    for (int c = 0; c < CD; c++) {
        unsigned a = g_hist1[c * NBIN + 2 * t];
        unsigned b = g_hist1[c * NBIN + 2 * t + 1];
        unsigned s = a + b;
        unsigned incl = s;
        for (int off = 1; off < 32; off <<= 1) {
            unsigned u = __shfl_up_sync(0xffffffffu, incl, off);
            if (lane >= off) incl += u;
        }
        if (lane == 31) swsum[warp] = incl;
        __syncthreads();
        if (t == 0) {
            unsigned run = 0;
#pragma unroll
            for (int w = 0; w < 8; w++) { swpre[w] = run; run += swsum[w]; }
            s_n = run;
        }
        __syncthreads();
        unsigned total = s_n;
        long long exclp = (long long)(incl - s + swpre[warp]);
        long long n = (long long)total;
        if (n == 0) {
            if (t == 0) { s_ncls[c] = 0; s_f05[c] = 0.0; s_f95[c] = 0.0; }
        } else {
            double p05 = 0.05 * (double)(n - 1);
            long long i05 = (long long)p05;
            double p95 = 0.95 * (double)(n - 1);
            long long i95 = (long long)p95;
            if (t == 0) {
                s_ncls[c] = total;
                s_f05[c] = p05 - (double)i05;
                s_f95[c] = p95 - (double)i95;
            }
            long long rr[4];
            rr[0] = i05; rr[1] = (i05 + 1 < n) ? i05 + 1 : i05;
            rr[2] = i95; rr[3] = (i95 + 1 < n) ? i95 + 1 : i95;
#pragma unroll
            for (int j = 0; j < 4; j++) {
                long long r = rr[j];
                if (r >= exclp && r < exclp + (long long)s) {
                    unsigned rem = (unsigned)(r - exclp);
                    if (rem < a) { spre[c * 4 + j] = PLO + 2 * t;     srank[c * 4 + j] = rem; }
                    else         { spre[c * 4 + j] = PLO + 2 * t + 1; srank[c * 4 + j] = rem - a; }
                }
            }
        }
        __syncthreads();
    }
    if (t == 0) {
        int mmax = 0;
        for (int c = 0; c < CD; c++) {
            int m = 0;
            for (int j = 0; j < 4; j++) {
                int pre = spre[c * 4 + j];
                if (pre < 0 || pre == SPIKE_PRE) continue;
                bool dup = false;
                for (int j2 = 0; j2 < j; j2++) if (spre[c * 4 + j2] == pre) { dup = true; break; }
                if (!dup) { sek[c * 4 + m] = pre & 0x1FFF; m++; }
            }
            for (int e = m; e < 4; e++) sek[c * 4 + e] = -1;
            utgt[c] = (sek[c * 4] >= 0) ? (((unsigned)c << 13) | (unsigned)sek[c * 4]) : 0xFFFFFFFFu;
            if (m > mmax) mmax = m;
        }
        s_m = mmax;
    }
    __syncthreads();

    // ---- fine matching over register-resident packed data (no re-read) ----
    int mm = s_m;
    if (mm == 1) {
        for (int i = 0; i < nsav; i++) {
            unsigned pks[4] = { pk_sav[i].x, pk_sav[i].y, pk_sav[i].z, pk_sav[i].w };
#pragma unroll
            for (int k = 0; k < 4; k++) {
                unsigned u = pks[k] >> 16;          // (c<<13)|key13
                if (u == utgt[u >> 13]) {
                    unsigned c4 = (u >> 13) * 4;
                    unsigned low = pks[k] & 0xFFFFu;
                    atomicAdd(&g_histF[c4 * 65536 + low], 1u);
                    atomicAdd(&g_chunk[c4 * 256 + (low >> 8)], 1u);
                }
            }
        }
    } else if (mm > 1) {
        for (int i = 0; i < nsav; i++) {
            unsigned pks[4] = { pk_sav[i].x, pk_sav[i].y, pk_sav[i].z, pk_sav[i].w };
#pragma unroll
            for (int k = 0; k < 4; k++) {
                unsigned pk = pks[k];
                int c = (int)(pk >> 29);
                int key = (int)((pk >> 16) & 0x1FFFu);
                for (int s = 0; s < mm; s++)
                    if (sek[c * 4 + s] == key) {
                        unsigned low = pk & 0xFFFFu;
                        atomicAdd(&g_histF[(c * 4 + s) * 65536 + low], 1u);
                        atomicAdd(&g_chunk[(c * 4 + s) * 256 + (low >> 8)], 1u);
                    }
            }
        }
    }

    // ---- last-block: select order statistics + EMA finalize ----
    __threadfence();
    if (t == 0) is_last = (atomicAdd(&g_done, 1u) == (unsigned)(gridDim.x - 1));
    __syncthreads();
    if (!is_last) return;

    for (int slot = warp; slot < NSLOT; slot += 8) {
        int pre = spre[slot];
        if (pre < 0 || pre == SPIKE_PRE) {
            if (lane == 0) sx[slot] = 0x3F800000u;   // spike or empty class
            continue;
        }
        int c = slot >> 2;
        int key = pre & 0x1FFF;
        int e = c * 4;
        for (int s = 0; s < 4; s++) if (sek[c * 4 + s] == key) { e = c * 4 + s; break; }
        const unsigned* hc = &g_chunk[e * 256];
        const unsigned* hf = &g_histF[e * 65536];
        unsigned rank = srank[slot];

        unsigned h[8]; unsigned sum = 0;
#pragma unroll
        for (int j = 0; j < 8; j++) { h[j] = hc[lane * 8 + j]; sum += h[j]; }
        unsigned v = sum;
        for (int off = 1; off < 32; off <<= 1) {
            unsigned u = __shfl_up_sync(0xffffffffu, v, off);
            if (lane >= off) v += u;
        }
        unsigned excl = v - sum;
        bool hit = (excl <= rank && rank < excl + sum);
        unsigned mball = __ballot_sync(0xffffffffu, hit);
        int srcl = __ffs(mball) - 1;
        int jc = 0; unsigned rem = 0;
        if (hit) {
            unsigned run = excl;
#pragma unroll
            for (int j = 0; j < 8; j++) {
                if (rank < run + h[j]) { jc = lane * 8 + j; rem = rank - run; break; }
                run += h[j];
            }
        }
        jc  = __shfl_sync(0xffffffffu, jc, srcl);
        rem = __shfl_sync(0xffffffffu, rem, srcl);

        unsigned f[8]; unsigned fsum = 0;
#pragma unroll
        for (int j = 0; j < 8; j++) { f[j] = hf[jc * 256 + lane * 8 + j]; fsum += f[j]; }
        unsigned fv = fsum;
        for (int off = 1; off < 32; off <<= 1) {
            unsigned u = __shfl_up_sync(0xffffffffu, fv, off);
            if (lane >= off) fv += u;
        }
        unsigned fexcl = fv - fsum;
        if (fexcl <= rem && rem < fexcl + fsum) {
            unsigned run = fexcl;
#pragma unroll
            for (int j = 0; j < 8; j++) {
                if (rem < run + f[j]) {
                    sx[slot] = ((unsigned)pre << 16) | (unsigned)(jc * 256 + lane * 8 + j);
                    break;
                }
                run += f[j];
            }
        }
    }
    __syncthreads();
    if (t < CD) {
        int c = t;
        float nmin, nmax;
        if (s_ncls[c] == 0) {
            nmin = emin[c]; nmax = emax[c];
        } else {
            float x0 = __uint_as_float(sx[c * 4 + 0]);
            float x1 = __uint_as_float(sx[c * 4 + 1]);
            float x2 = __uint_as_float(sx[c * 4 + 2]);
            float x3 = __uint_as_float(sx[c * 4 + 3]);
            float bmin = (float)((double)x0 + s_f05[c] * ((double)x1 - (double)x0));
            float bmax = (float)((double)x2 + s_f95[c] * ((double)x3 - (double)x2));
            bool ini = einit[c] != 0;
            nmin = ini ? (0.99f * emin[c] + 0.01f * bmin) : bmin;
            nmax = ini ? (0.99f * emax[c] + 0.01f * bmax) : bmax;
        }
        g_newmin[c] = nmin; g_newmax[c] = nmax;
    }
}

// ---------------- K2: gamma map + feature scaling (HBM-bound, at ~71% DRAM floor) --
// 512-thread blocks; 1024 voxel-groups per block (two 512-wide tiles).
__global__ void k_scale(const float4* __restrict__ ft, const float* __restrict__ ranks,
                        float* __restrict__ out) {
    __shared__ float smin[CD], sinv[CD], sadd[CD], smax[CD], sint[CD];
    if (threadIdx.x < CD) {
        int c = threadIdx.x;
        float mn = g_newmin[c], mx = g_newmax[c];
        smin[c] = mn; smax[c] = mx;
        sint[c] = 1.0f - ranks[c] / 4.0f;
        if (mx > mn) { sinv[c] = 1.0f / (mx - mn + 1e-8f); sadd[c] = 0.0f; }
        else         { sinv[c] = 0.0f;                     sadd[c] = 0.5f; }
    }
    __syncthreads();
    int g0 = blockIdx.x * 1024 + threadIdx.x;  // tile 0
    int g1 = g0 + 512;                          // tile 1
    uint4 pa = ((const uint4*)g_packed)[g0];
    uint4 pb = ((const uint4*)g_packed)[g1];
    unsigned pks[8] = { pa.x, pa.y, pa.z, pa.w, pb.x, pb.y, pb.z, pb.w };

    float gm[8];
#pragma unroll
    for (int k = 0; k < 8; k++) {
        unsigned pk = pks[k];
        int c = (int)(pk >> 29);
        float cv = __uint_as_float((pk & 0x1FFFFFFFu) | 0x20000000u);
        float mn = smin[c], mx = smax[c];
        float cl = fminf(fmaxf(cv, mn), mx);
        float nr = (cl - mn) * sinv[c] + sadd[c];
        gm[k] = 1.0f + sint[c] * (1.0f + 0.5f * (1.0f - nr));
    }
    __stcs((float4*)(out + NFEAT) + g0, make_float4(gm[0], gm[1], gm[2], gm[3]));
    __stcs((float4*)(out + NFEAT) + g1, make_float4(gm[4], gm[5], gm[6], gm[7]));

    int b = (g0 >= Q4) ? 1 : 0;                 // uniform per block (Q4 = 216*1024)
    size_t fbase = (size_t)(b * FD) * Q4 + (size_t)(g0 - b * Q4);
    float4* o4 = (float4*)out;
#pragma unroll 4
    for (int f = 0; f < FD; f++) {
        size_t off = fbase + (size_t)f * Q4;
        float4 x0 = __ldcs(&ft[off]);
        float4 x1 = __ldcs(&ft[off + 512]);
        x0.x *= gm[0]; x0.y *= gm[1]; x0.z *= gm[2]; x0.w *= gm[3];
        x1.x *= gm[4]; x1.y *= gm[5]; x1.z *= gm[6]; x1.w *= gm[7];
        __stcs(&o4[off], x0);
        __stcs(&o4[off + 512], x1);
    }
}

// ---------------- launch ----------------
extern "C" void kernel_launch(void* const* d_in, const int* in_sizes, int n_in,
                              void* d_out, int out_size) {
    const float* feat          = (const float*)d_in[0];
    const float* logits        = (const float*)d_in[1];
    const int*   labels        = (const int*)d_in[2];
    const float* ranks         = (const float*)d_in[3];
    const float* emin          = (const float*)d_in[4];
    const float* emax          = (const float*)d_in[5];
    const unsigned char* einit = (const unsigned char*)d_in[6];
    float* out = (float*)d_out;
    (void)in_sizes; (void)n_in; (void)out_size;

    k_zero<<<8, 256>>>();
    k_fused<<<HGRID, 256>>>((const float4*)logits, (const int4*)labels, emin, emax, einit);
    k_scale<<<SGRID, 512>>>((const float4*)feat, ranks, out);
}

// round 17
// speedup vs baseline: 1.0380x; 1.0380x over previous
#include <cuda_runtime.h>

// Fixed problem shapes
#define BD 2
#define FD 32
#define CD 5
#define DHW 884736           // 96^3
#define Q4 (DHW/4)           // 221184
#define NVOX (BD*DHW)        // 1769472
#define NG (NVOX/4)          // 442368
#define NFEAT (BD*FD*DHW)    // 56623104
#define PLO 15872            // conf in (0.19,1.0] -> 16-bit prefix within [PLO, PLO+512)
#define NBIN 512
#define NSLOT 20             // 5 classes x 4 order statistics
#define NENT 20
#define SPIKE_PRE 16256      // 0x3F80 : bin containing only conf == 1.0
#define HGRID 592
#define SGRID (NG/512)       // 864 blocks x 256 threads x 2 tiles (R12 measured best)

// ---------------- device scratch ----------------
__device__ __align__(16) unsigned g_packed[NVOX];        // label<<29 | (conf bits & 0x1FFFFFFF)
__device__ unsigned g_hist1[CD * NBIN];
__device__ __align__(16) unsigned g_histF[NENT * 65536]; // fine 16-bit histograms (5.24 MB)
__device__ __align__(16) unsigned g_chunk[NENT * 256];   // 256-chunk sums per entry
__device__ float    g_newmin[CD], g_newmax[CD];
__device__ unsigned g_done;

// ---------------- K0: zero hist1 + done ----------------
__global__ void k_zero() {
    int i = blockIdx.x * blockDim.x + threadIdx.x;
    int stride = gridDim.x * blockDim.x;
    for (int j = i; j < CD * NBIN; j += stride) g_hist1[j] = 0;
    if (i == 0) g_done = 0;
}

// ---------------- K1: confidence + packed store + level-1 hist + zero histF -------
__device__ __forceinline__ float conf5(float a, float b, float c, float d, float e) {
    float y0 = a * 10.0f, y1 = b * 10.0f, y2 = c * 10.0f, y3 = d * 10.0f, y4 = e * 10.0f;
    float m = fmaxf(fmaxf(fmaxf(y0, y1), fmaxf(y2, y3)), y4);
    float s = __expf(y0 - m) + __expf(y1 - m) + __expf(y2 - m) + __expf(y3 - m) + __expf(y4 - m);
    return __fdividef(1.0f, s);
}

__global__ void k_conf(const float4* __restrict__ lg, const int4* __restrict__ lb) {
    __shared__ unsigned sh[CD * NBIN];
    for (int j = threadIdx.x; j < CD * NBIN; j += blockDim.x) sh[j] = 0;
    __syncthreads();
    int stride = gridDim.x * blockDim.x;
    int tid = blockIdx.x * blockDim.x + threadIdx.x;
    // zero fine histograms + chunk sums for the following k_fine
    {
        uint4 z = make_uint4(0, 0, 0, 0);
        for (int j = tid; j < (NENT * 65536) / 4; j += stride) __stcs((uint4*)g_histF + j, z);
        for (int j = tid; j < (NENT * 256) / 4; j += stride)   ((uint4*)g_chunk)[j] = z;
    }
    for (int g = tid; g < NG; g += stride) {
        int v = g * 4;
        int b = (v >= DHW) ? 1 : 0;
        int s4 = g - b * Q4;
        size_t base = (size_t)(b * CD) * Q4 + (size_t)s4;
        float4 L0 = __ldcs(&lg[base]);
        float4 L1 = __ldcs(&lg[base + Q4]);
        float4 L2 = __ldcs(&lg[base + 2 * (size_t)Q4]);
        float4 L3 = __ldcs(&lg[base + 3 * (size_t)Q4]);
        float4 L4 = __ldcs(&lg[base + 4 * (size_t)Q4]);
        float cf[4];
        cf[0] = conf5(L0.x, L1.x, L2.x, L3.x, L4.x);
        cf[1] = conf5(L0.y, L1.y, L2.y, L3.y, L4.y);
        cf[2] = conf5(L0.z, L1.z, L2.z, L3.z, L4.z);
        cf[3] = conf5(L0.w, L1.w, L2.w, L3.w, L4.w);
        int4 li = __ldcs(&lb[g]);
        int cc[4] = { li.x, li.y, li.z, li.w };
        unsigned pk[4];
#pragma unroll
        for (int k = 0; k < 4; k++) {
            unsigned bits = __float_as_uint(cf[k]);
            pk[k] = ((unsigned)cc[k] << 29) | (bits & 0x1FFFFFFFu);
            unsigned idx = (bits >> 16) - PLO;
            if (idx < NBIN) atomicAdd(&sh[cc[k] * NBIN + idx], 1u);
        }
        // default store: keep packed L2-resident for k_fine and k_scale (7 MB << L2)
        ((uint4*)g_packed)[g] = make_uint4(pk[0], pk[1], pk[2], pk[3]);
    }
    __syncthreads();
    for (int j = threadIdx.x; j < CD * NBIN; j += blockDim.x) {
        unsigned u = sh[j];
        if (u) atomicAdd(&g_hist1[j], u);
    }
}

// ---------------- K2: find2 + fine-histogram pass + last-block select/finalize ----
__global__ void k_fine(const float* __restrict__ emin, const float* __restrict__ emax,
                       const unsigned char* __restrict__ einit) {
    __shared__ int      spre[NSLOT];
    __shared__ unsigned srank[NSLOT];
    __shared__ int      sek[NENT];
    __shared__ unsigned utgt[CD];       // fast path: (c<<13)|key, 0xFFFFFFFF = none
    __shared__ int      s_m;
    __shared__ unsigned swsum[8], swpre[8];
    __shared__ unsigned s_n;
    __shared__ unsigned s_ncls[CD];
    __shared__ double   s_f05[CD], s_f95[CD];
    __shared__ unsigned sx[NSLOT];
    __shared__ bool     is_last;

    int t = threadIdx.x, lane = t & 31, warp = t >> 5;
    if (t < NSLOT) { spre[t] = -1; srank[t] = 0; }
    __syncthreads();

    // ---- find2: scan 512-bin prefix histogram per class (2 bins/thread) ----
    for (int c = 0; c < CD; c++) {
        unsigned a = g_hist1[c * NBIN + 2 * t];
        unsigned b = g_hist1[c * NBIN + 2 * t + 1];
        unsigned s = a + b;
        unsigned incl = s;
        for (int off = 1; off < 32; off <<= 1) {
            unsigned u = __shfl_up_sync(0xffffffffu, incl, off);
            if (lane >= off) incl += u;
        }
        if (lane == 31) swsum[warp] = incl;
        __syncthreads();
        if (t == 0) {
            unsigned run = 0;
#pragma unroll
            for (int w = 0; w < 8; w++) { swpre[w] = run; run += swsum[w]; }
            s_n = run;
        }
        __syncthreads();
        unsigned total = s_n;
        long long exclp = (long long)(incl - s + swpre[warp]);
        long long n = (long long)total;
        if (n == 0) {
            if (t == 0) { s_ncls[c] = 0; s_f05[c] = 0.0; s_f95[c] = 0.0; }
        } else {
            double p05 = 0.05 * (double)(n - 1);
            long long i05 = (long long)p05;
            double p95 = 0.95 * (double)(n - 1);
            long long i95 = (long long)p95;
            if (t == 0) {
                s_ncls[c] = total;
                s_f05[c] = p05 - (double)i05;
                s_f95[c] = p95 - (double)i95;
            }
            long long rr[4];
            rr[0] = i05; rr[1] = (i05 + 1 < n) ? i05 + 1 : i05;
            rr[2] = i95; rr[3] = (i95 + 1 < n) ? i95 + 1 : i95;
#pragma unroll
            for (int j = 0; j < 4; j++) {
                long long r = rr[j];
                if (r >= exclp && r < exclp + (long long)s) {
                    unsigned rem = (unsigned)(r - exclp);
                    if (rem < a) { spre[c * 4 + j] = PLO + 2 * t;     srank[c * 4 + j] = rem; }
                    else         { spre[c * 4 + j] = PLO + 2 * t + 1; srank[c * 4 + j] = rem - a; }
                }
            }
        }
        __syncthreads();
    }
    // compact entry list: dedup non-spike prefixes per class
    if (t == 0) {
        int mmax = 0;
        for (int c = 0; c < CD; c++) {
            int m = 0;
            for (int j = 0; j < 4; j++) {
                int pre = spre[c * 4 + j];
                if (pre < 0 || pre == SPIKE_PRE) continue;
                bool dup = false;
                for (int j2 = 0; j2 < j; j2++) if (spre[c * 4 + j2] == pre) { dup = true; break; }
                if (!dup) { sek[c * 4 + m] = pre & 0x1FFF; m++; }
            }
            for (int e = m; e < 4; e++) sek[c * 4 + e] = -1;
            utgt[c] = (sek[c * 4] >= 0) ? (((unsigned)c << 13) | (unsigned)sek[c * 4]) : 0xFFFFFFFFu;
            if (m > mmax) mmax = m;
        }
        s_m = mmax;
    }
    __syncthreads();

    // ---- fine pass over packed stream (mostly L2-resident) ----
    int mm = s_m;
    int stride = gridDim.x * blockDim.x;
    if (mm == 1) {
        // fast path: single key per class -> one compare per voxel
        for (int g = blockIdx.x * blockDim.x + t; g < NG; g += stride) {
            uint4 p4 = ((const uint4*)g_packed)[g];
            unsigned pks[4] = { p4.x, p4.y, p4.z, p4.w };
#pragma unroll
            for (int k = 0; k < 4; k++) {
                unsigned u = pks[k] >> 16;          // (c<<13)|key13
                if (u == utgt[u >> 13]) {
                    unsigned c4 = (u >> 13) * 4;
                    unsigned low = pks[k] & 0xFFFFu;
                    atomicAdd(&g_histF[c4 * 65536 + low], 1u);
                    atomicAdd(&g_chunk[c4 * 256 + (low >> 8)], 1u);
                }
            }
        }
    } else if (mm > 1) {
        for (int g = blockIdx.x * blockDim.x + t; g < NG; g += stride) {
            uint4 p4 = ((const uint4*)g_packed)[g];
            unsigned pks[4] = { p4.x, p4.y, p4.z, p4.w };
#pragma unroll
            for (int k = 0; k < 4; k++) {
                unsigned pk = pks[k];
                int c = (int)(pk >> 29);
                int key = (int)((pk >> 16) & 0x1FFFu);
                for (int s = 0; s < mm; s++)
                    if (sek[c * 4 + s] == key) {
                        unsigned low = pk & 0xFFFFu;
                        atomicAdd(&g_histF[(c * 4 + s) * 65536 + low], 1u);
                        atomicAdd(&g_chunk[(c * 4 + s) * 256 + (low >> 8)], 1u);
                    }
            }
        }
    }

    // ---- last-block: select order statistics via chunk sums, then EMA finalize ----
    __threadfence();
    if (t == 0) is_last = (atomicAdd(&g_done, 1u) == (unsigned)(gridDim.x - 1));
    __syncthreads();
    if (!is_last) return;

    for (int slot = warp; slot < NSLOT; slot += 8) {
        int pre = spre[slot];
        if (pre < 0 || pre == SPIKE_PRE) {
            if (lane == 0) sx[slot] = 0x3F800000u;   // spike or empty class
            continue;
        }
        int c = slot >> 2;
        int key = pre & 0x1FFF;
        int e = c * 4;
        for (int s = 0; s < 4; s++) if (sek[c * 4 + s] == key) { e = c * 4 + s; break; }
        const unsigned* hc = &g_chunk[e * 256];
        const unsigned* hf = &g_histF[e * 65536];
        unsigned rank = srank[slot];

        unsigned h[8]; unsigned sum = 0;
#pragma unroll
        for (int j = 0; j < 8; j++) { h[j] = hc[lane * 8 + j]; sum += h[j]; }
        unsigned v = sum;
        for (int off = 1; off < 32; off <<= 1) {
            unsigned u = __shfl_up_sync(0xffffffffu, v, off);
            if (lane >= off) v += u;
        }
        unsigned excl = v - sum;
        bool hit = (excl <= rank && rank < excl + sum);
        unsigned mball = __ballot_sync(0xffffffffu, hit);
        int srcl = __ffs(mball) - 1;
        int jc = 0; unsigned rem = 0;
        if (hit) {
            unsigned run = excl;
#pragma unroll
            for (int j = 0; j < 8; j++) {
                if (rank < run + h[j]) { jc = lane * 8 + j; rem = rank - run; break; }
                run += h[j];
            }
        }
        jc  = __shfl_sync(0xffffffffu, jc, srcl);
        rem = __shfl_sync(0xffffffffu, rem, srcl);

        unsigned f[8]; unsigned fsum = 0;
#pragma unroll
        for (int j = 0; j < 8; j++) { f[j] = hf[jc * 256 + lane * 8 + j]; fsum += f[j]; }
        unsigned fv = fsum;
        for (int off = 1; off < 32; off <<= 1) {
            unsigned u = __shfl_up_sync(0xffffffffu, fv, off);
            if (lane >= off) fv += u;
        }
        unsigned fexcl = fv - fsum;
        if (fexcl <= rem && rem < fexcl + fsum) {
            unsigned run = fexcl;
#pragma unroll
            for (int j = 0; j < 8; j++) {
                if (rem < run + f[j]) {
                    sx[slot] = ((unsigned)pre << 16) | (unsigned)(jc * 256 + lane * 8 + j);
                    break;
                }
                run += f[j];
            }
        }
    }
    __syncthreads();
    if (t < CD) {
        int c = t;
        float nmin, nmax;
        if (s_ncls[c] == 0) {
            nmin = emin[c]; nmax = emax[c];
        } else {
            float x0 = __uint_as_float(sx[c * 4 + 0]);
            float x1 = __uint_as_float(sx[c * 4 + 1]);
            float x2 = __uint_as_float(sx[c * 4 + 2]);
            float x3 = __uint_as_float(sx[c * 4 + 3]);
            float bmin = (float)((double)x0 + s_f05[c] * ((double)x1 - (double)x0));
            float bmax = (float)((double)x2 + s_f95[c] * ((double)x3 - (double)x2));
            bool ini = einit[c] != 0;
            nmin = ini ? (0.99f * emin[c] + 0.01f * bmin) : bmin;
            nmax = ini ? (0.99f * emax[c] + 0.01f * bmax) : bmax;
        }
        g_newmin[c] = nmin; g_newmax[c] = nmax;
    }
}

// ---------------- K3: gamma map + feature scaling (HBM-bound, R12 shape) ----------
// 256-thread blocks; each block owns 512 consecutive voxel-groups (two tiles).
// Q4 = 432*512, so the batch index is uniform within a block.
__global__ void k_scale(const float4* __restrict__ ft, const float* __restrict__ ranks,
                        float* __restrict__ out) {
    __shared__ float smin[CD], sinv[CD], sadd[CD], smax[CD], sint[CD];
    if (threadIdx.x < CD) {
        int c = threadIdx.x;
        float mn = g_newmin[c], mx = g_newmax[c];
        smin[c] = mn; smax[c] = mx;
        sint[c] = 1.0f - ranks[c] / 4.0f;
        if (mx > mn) { sinv[c] = 1.0f / (mx - mn + 1e-8f); sadd[c] = 0.0f; }
        else         { sinv[c] = 0.0f;                     sadd[c] = 0.5f; }
    }
    __syncthreads();
    int g0 = blockIdx.x * 512 + threadIdx.x;   // tile 0
    int g1 = g0 + 256;                          // tile 1
    uint4 pa = ((const uint4*)g_packed)[g0];
    uint4 pb = ((const uint4*)g_packed)[g1];
    unsigned pks[8] = { pa.x, pa.y, pa.z, pa.w, pb.x, pb.y, pb.z, pb.w };

    float gm[8];
#pragma unroll
    for (int k = 0; k < 8; k++) {
        unsigned pk = pks[k];
        int c = (int)(pk >> 29);
        float cv = __uint_as_float((pk & 0x1FFFFFFFu) | 0x20000000u);
        float mn = smin[c], mx = smax[c];
        float cl = fminf(fmaxf(cv, mn), mx);
        float nr = (cl - mn) * sinv[c] + sadd[c];
        gm[k] = 1.0f + sint[c] * (1.0f + 0.5f * (1.0f - nr));
    }
    __stcs((float4*)(out + NFEAT) + g0, make_float4(gm[0], gm[1], gm[2], gm[3]));
    __stcs((float4*)(out + NFEAT) + g1, make_float4(gm[4], gm[5], gm[6], gm[7]));

    int b = (g0 >= Q4) ? 1 : 0;                 // uniform per block
    size_t fbase = (size_t)(b * FD) * Q4 + (size_t)(g0 - b * Q4);
    float4* o4 = (float4*)out;
#pragma unroll 8
    for (int f = 0; f < FD; f++) {
        size_t off = fbase + (size_t)f * Q4;
        float4 x0 = __ldcs(&ft[off]);
        float4 x1 = __ldcs(&ft[off + 256]);
        x0.x *= gm[0]; x0.y *= gm[1]; x0.z *= gm[2]; x0.w *= gm[3];
        x1.x *= gm[4]; x1.y *= gm[5]; x1.z *= gm[6]; x1.w *= gm[7];
        __stcs(&o4[off], x0);
        __stcs(&o4[off + 256], x1);
    }
}

// ---------------- launch ----------------
extern "C" void kernel_launch(void* const* d_in, const int* in_sizes, int n_in,
                              void* d_out, int out_size) {
    const float* feat          = (const float*)d_in[0];
    const float* logits        = (const float*)d_in[1];
    const int*   labels        = (const int*)d_in[2];
    const float* ranks         = (const float*)d_in[3];
    const float* emin          = (const float*)d_in[4];
    const float* emax          = (const float*)d_in[5];
    const unsigned char* einit = (const unsigned char*)d_in[6];
    float* out = (float*)d_out;
    (void)in_sizes; (void)n_in; (void)out_size;

    k_zero<<<148, 256>>>();
    k_conf<<<HGRID, 256>>>((const float4*)logits, (const int4*)labels);
    k_fine<<<HGRID, 256>>>(emin, emax, einit);
    k_scale<<<SGRID, 256>>>((const float4*)feat, ranks, out);
}